// round 8
// baseline (speedup 1.0000x reference)
#include <cuda_runtime.h>
#include <cuda_bf16.h>
#include <cuda_fp16.h>
#include <cstdint>

#define L_RES 512
#define C_S   256
#define C_Z   128
#define LN_EPS 1e-5f

// ---------------------------------------------------------------------------
// Device scratch
// ---------------------------------------------------------------------------
__device__ __align__(16) float g_u[L_RES * C_S];        // LayerNorm'd embeddings
__device__ __align__(16) float g_zjb[L_RES * C_Z];      // u @ W2 + b_pair
__device__ __align__(16) float g_zib[L_RES * C_Z];      // u @ W1
__device__ __align__(16) __half g_w3t[C_Z * C_S];       // W3^T fp16  [z][c]

// ---------------------------------------------------------------------------
// Base-PTX tensor helpers (valid on compute_103)
// ---------------------------------------------------------------------------
__device__ __forceinline__ uint32_t smem_u32(const void* p) {
    uint32_t a;
    asm("{ .reg .u64 t; cvta.to.shared.u64 t, %1; cvt.u32.u64 %0, t; }"
        : "=r"(a) : "l"(p));
    return a;
}

__device__ __forceinline__ void ldsm_x4(uint32_t& r0, uint32_t& r1,
                                        uint32_t& r2, uint32_t& r3, uint32_t addr) {
    asm volatile("ldmatrix.sync.aligned.m8n8.x4.shared.b16 {%0,%1,%2,%3}, [%4];"
                 : "=r"(r0), "=r"(r1), "=r"(r2), "=r"(r3) : "r"(addr));
}

__device__ __forceinline__ void mma16816(float* c, const uint32_t* a, const uint32_t* b) {
    asm volatile(
        "mma.sync.aligned.m16n8k16.row.col.f32.f16.f16.f32 "
        "{%0,%1,%2,%3}, {%4,%5,%6,%7}, {%8,%9}, {%0,%1,%2,%3};"
        : "+f"(c[0]), "+f"(c[1]), "+f"(c[2]), "+f"(c[3])
        : "r"(a[0]), "r"(a[1]), "r"(a[2]), "r"(a[3]), "r"(b[0]), "r"(b[1]));
}

// ---------------------------------------------------------------------------
// Kernel 1: gather + LayerNorm + zjb (u@W2 + b) + zib (u@W1)
// ---------------------------------------------------------------------------
__global__ void prep_kernel(const int* __restrict__ seq,
                            const int* __restrict__ chain,
                            const int* __restrict__ ridx,
                            const float* __restrict__ E_aa,
                            const float* __restrict__ E_pos,
                            const float* __restrict__ E_chain,
                            const float* __restrict__ W_pair,
                            const float* __restrict__ b_pair,
                            const float* __restrict__ ln_w,
                            const float* __restrict__ ln_b,
                            float* __restrict__ out_s)
{
    int i = blockIdx.x;
    int t = threadIdx.x;            // 256 threads == C_S

    __shared__ float u_s[C_S];
    __shared__ float red1[8], red2[8];
    __shared__ float mu_sh, rstd_sh;

    int sq = seq[i], ci = chain[i], ri = ridx[i];
    float v = E_aa[sq * C_S + t] + E_pos[ri * C_S + t] + E_chain[ci * C_S + t];
    out_s[i * C_S + t] = v;

    // fused sum + sumsq reduction (single pass)
    float s1 = v, s2 = v * v;
    #pragma unroll
    for (int o = 16; o; o >>= 1) {
        s1 += __shfl_xor_sync(0xffffffffu, s1, o);
        s2 += __shfl_xor_sync(0xffffffffu, s2, o);
    }
    if ((t & 31) == 0) { red1[t >> 5] = s1; red2[t >> 5] = s2; }
    __syncthreads();
    if (t == 0) {
        float a1 = 0.f, a2 = 0.f;
        #pragma unroll
        for (int w = 0; w < 8; w++) { a1 += red1[w]; a2 += red2[w]; }
        float mu = a1 * (1.f / C_S);
        float var = a2 * (1.f / C_S) - mu * mu;
        mu_sh = mu;
        rstd_sh = rsqrtf(var + LN_EPS);
    }
    __syncthreads();

    float uu = (v - mu_sh) * rstd_sh * ln_w[t] + ln_b[t];
    g_u[i * C_S + t] = uu;
    u_s[t] = uu;
    __syncthreads();

    // 8 independent accumulator chains (MLP=8)
    int z = t & (C_Z - 1);
    int base = (t < C_Z) ? C_S : 0;
    const float* Wz = W_pair + (size_t)base * C_Z + z;
    float a[8];
    #pragma unroll
    for (int q = 0; q < 8; q++) a[q] = 0.f;
    #pragma unroll 2
    for (int c = 0; c < C_S; c += 8) {
        #pragma unroll
        for (int q = 0; q < 8; q++)
            a[q] += u_s[c + q] * Wz[(c + q) * C_Z];
    }
    float acc = ((a[0] + a[1]) + (a[2] + a[3])) + ((a[4] + a[5]) + (a[6] + a[7]));
    if (t < C_Z) g_zjb[i * C_Z + z] = acc + b_pair[z];
    else         g_zib[i * C_Z + z] = acc;
}

// ---------------------------------------------------------------------------
// Kernel 2: W3 -> transposed fp16:  g_w3t[z*C_S + c]
// ---------------------------------------------------------------------------
__global__ void w3split_kernel(const float* __restrict__ W_pair)
{
    int c = blockIdx.x;             // 0..255
    int z = threadIdx.x;            // 0..127
    g_w3t[z * C_S + c] = __float2half_rn(W_pair[(2 * C_S + c) * C_Z + z]);
}

// ---------------------------------------------------------------------------
// Kernel 3: symmetric mma.sync fp16 pair kernel.
// zx[i,j,:] is symmetric in (i,j): compute only blocks with j0 >= i0 and
// write both z[i,j,:] (direct) and z[j,i,:] (mirror, when tile(j) > tile(i)).
// 320 blocks (62.5% of the MMA work), 1D grid, decode (by, jgrel).
// Exactly-once coverage:
//   tile(a)<tile(b): direct from (tile(a), j=b)
//   tile(a)==tile(b): direct from (tile(a), j=b)  (mirror disabled on diagonal)
//   tile(a)>tile(b): mirror from (tile(b), j=a)
// ---------------------------------------------------------------------------
#define NCHUNK 8                      // K chunks of 32

// SMEM layout (bytes)
#define SM_W3H   0                    // [z=128][c=256] fp16 swizzled  65536
#define SM_AP    65536                // 2 bufs x [i=128][128B]        32768
#define SM_ECP   98304                // 4 x 132 f32                    2112
#define SM_ZJB   100416               // 4 x 128 f32 (zjb[j0..j0+3])    2048
#define SM_ZIBJ  102464               // 4 x 128 f32 (zib[j0..j0+3])    2048
#define SM_UJ    104512               // 4 x 256 f32                    4096
#define SM_CH    108608               // 128 int                         512
#define SM_RI    109120               // 128 int                         512
#define SMEM_TOTAL 109632

// swizzled W3 smem byte offset for (z, c16) ; c16 = c/8 in [0,32)
__device__ __forceinline__ uint32_t w3_off(int z, int c16) {
    return (uint32_t)(z * 512 + ((c16 & ~7) + ((c16 ^ (z & 7)) & 7)) * 16);
}
// swizzled A' byte offset for (row, chunk) ; chunk in [0,4)
__device__ __forceinline__ uint32_t ap_off(int row, int ch) {
    return (uint32_t)(row * 128 + (ch ^ (row & 7)) * 16);
}

__device__ __forceinline__ void load_u(float4* ur, int i0, int kcg, int t) {
    const int r = t >> 1, half = t & 1;
    const float4* up = (const float4*)(g_u + (size_t)(i0 + r) * C_S + kcg * 32 + half * 16);
    ur[0] = up[0]; ur[1] = up[1]; ur[2] = up[2]; ur[3] = up[3];
}

__device__ __forceinline__ void pack_store(char* smem, int buf, const float4* ur,
                                           int jg, int kcg, int t)
{
    const int r = t >> 1, half = t & 1;
    const int c0 = kcg * 32 + half * 16;
    const float4* jp = (const float4*)((const float*)(smem + SM_UJ) + jg * C_S + c0);

    uint32_t hi[8];
    #pragma unroll
    for (int q = 0; q < 4; q++) {
        float4 u = ur[q];
        float4 w = jp[q];
        __half2 h01 = __floats2half2_rn(u.x * w.x, u.y * w.y);
        __half2 h23 = __floats2half2_rn(u.z * w.z, u.w * w.w);
        hi[2 * q]     = *reinterpret_cast<uint32_t*>(&h01);
        hi[2 * q + 1] = *reinterpret_cast<uint32_t*>(&h23);
    }
    char* apc = smem + SM_AP + buf * 16384;
    int ch0 = half * 2;
    *(uint4*)(apc + ap_off(r, ch0))     = make_uint4(hi[0], hi[1], hi[2], hi[3]);
    *(uint4*)(apc + ap_off(r, ch0 + 1)) = make_uint4(hi[4], hi[5], hi[6], hi[7]);
}

__global__ __launch_bounds__(256, 2)
void pair_kernel(const int* __restrict__ chain,
                 const int* __restrict__ ridx,
                 const float* __restrict__ E_cp,
                 const float* __restrict__ E_rp,
                 float* __restrict__ out_z)
{
    extern __shared__ char smem[];
    const uint32_t sbase = smem_u32(smem);
    const int t = threadIdx.x;           // 256
    const int lane = t & 31, wid = t >> 5;
    const int wm = wid >> 2;             // 0..1  (M)
    const int wn = wid & 3;              // 0..3  (N)

    // decode triangular block id -> (by, jgrel)
    const int b = blockIdx.x;
    int by, jgrel;
    if (b < 128)      { by = 0; jgrel = b; }
    else if (b < 224) { by = 1; jgrel = b - 128; }
    else if (b < 288) { by = 2; jgrel = b - 224; }
    else              { by = 3; jgrel = b - 288; }
    const int i0 = by * 128;
    const int j0 = i0 + jgrel * 4;
    const bool mirror = (jgrel >= 32);   // tile(j0) > by

    float* ecp_s = (float*)(smem + SM_ECP);
    float* zjb_s = (float*)(smem + SM_ZJB);
    float* zib_s = (float*)(smem + SM_ZIBJ);
    float* uj_s  = (float*)(smem + SM_UJ);
    int*   ch_s  = (int*)  (smem + SM_CH);
    int*   ri_s  = (int*)  (smem + SM_RI);

    // ---- prologue: stage W3 (swizzled), ecp, zjb/zib(j), uj, chain/ridx ----
    for (int idx = t; idx < 4096; idx += 256) {       // 16B chunks
        int z = idx >> 5, c16 = idx & 31;
        uint4 v = *(const uint4*)(g_w3t + (size_t)z * C_S + c16 * 8);
        *(uint4*)(smem + SM_W3H + w3_off(z, c16)) = v;
    }
    for (int idx = t; idx < 4 * C_Z; idx += 256)
        ecp_s[(idx >> 7) * 132 + (idx & 127)] = E_cp[idx];
    for (int idx = t; idx < 4 * C_Z; idx += 256) {
        zjb_s[idx] = g_zjb[(j0 + (idx >> 7)) * C_Z + (idx & 127)];
        zib_s[idx] = g_zib[(j0 + (idx >> 7)) * C_Z + (idx & 127)];
    }
    for (int idx = t; idx < 4 * C_S; idx += 256)
        uj_s[idx] = g_u[(j0 + (idx >> 8)) * C_S + (idx & 255)];
    if (t < 128) { ch_s[t] = chain[i0 + t]; ri_s[t] = ridx[i0 + t]; }

    int cj[4], rj[4];
    #pragma unroll
    for (int jj = 0; jj < 4; jj++) { cj[jj] = chain[j0 + jj]; rj[jj] = ridx[j0 + jj]; }
    __syncthreads();

    // lane address components (ldmatrix)
    const int arow_l = lane & 15;
    const int achk_l = lane >> 4;
    const int bgrp   = lane >> 3;
    const int bz_l   = ((bgrp >> 1) << 3) + (lane & 7);
    const int bco    = bgrp & 1;

    float4 ur[4];
    load_u(ur, i0, 0, t);                 // prefetch chunk 0

    #pragma unroll 1
    for (int jg = 0; jg < 4; jg++) {
        float acc[4][4][4];
        #pragma unroll
        for (int mt = 0; mt < 4; mt++)
            #pragma unroll
            for (int nt = 0; nt < 4; nt++)
                #pragma unroll
                for (int q = 0; q < 4; q++) acc[mt][nt][q] = 0.f;

        #pragma unroll 1
        for (int kcg = 0; kcg < NCHUNK; kcg++) {
            pack_store(smem, kcg & 1, ur, jg, kcg, t);
            __syncthreads();
            load_u(ur, i0, (kcg < NCHUNK - 1) ? kcg + 1 : 0, t);

            const uint32_t apb = sbase + SM_AP + (kcg & 1) * 16384;
            #pragma unroll
            for (int kk = 0; kk < 2; kk++) {
                uint32_t bh[4][2];
                #pragma unroll
                for (int pair = 0; pair < 2; pair++) {
                    int z   = wn * 32 + pair * 16 + bz_l;
                    int c16 = kcg * 4 + kk * 2 + bco;
                    uint32_t ad = sbase + SM_W3H + w3_off(z, c16);
                    ldsm_x4(bh[pair*2][0], bh[pair*2][1], bh[pair*2+1][0], bh[pair*2+1][1], ad);
                }
                uint32_t ahf[4][4];
                #pragma unroll
                for (int mt = 0; mt < 4; mt++) {
                    int row = wm * 64 + mt * 16 + arow_l;
                    int chh = kk * 2 + achk_l;
                    ldsm_x4(ahf[mt][0], ahf[mt][1], ahf[mt][2], ahf[mt][3],
                            apb + ap_off(row, chh));
                }
                #pragma unroll
                for (int mt = 0; mt < 4; mt++)
                    #pragma unroll
                    for (int nt = 0; nt < 4; nt++)
                        mma16816(acc[mt][nt], ahf[mt], bh[nt]);
            }
        }

        // ---- epilogue for this j ----
        const int g = lane >> 2, tig = lane & 3;
        #pragma unroll
        for (int mt = 0; mt < 4; mt++) {
            #pragma unroll
            for (int h = 0; h < 2; h++) {
                int row_l = wm * 64 + mt * 16 + g + h * 8;
                int ci = ch_s[row_l], ri = ri_s[row_l];
                int samec = (ci == cj[jg]);
                int dd = ri - rj[jg];
                int dcl = dd < -32 ? -32 : (dd > 32 ? 32 : dd);

                // direct: z[i0+row_l, j0+jg, :]
                {
                    int cp = ci * 2 + cj[jg];
                    int rp = samec ? (dcl + 32) : 65;
                    const float* erow = E_rp + (size_t)rp * C_Z;
                    const float* crow = ecp_s + cp * 132;
                    const float* zjr  = zjb_s + jg * C_Z;
                    const float* zir  = g_zib + (size_t)(i0 + row_l) * C_Z;
                    float* orow = out_z + ((size_t)(i0 + row_l) * L_RES + (j0 + jg)) * C_Z;
                    #pragma unroll
                    for (int nt = 0; nt < 4; nt++) {
                        int col = wn * 32 + nt * 8 + tig * 2;
                        float2 zi2 = *(const float2*)(zir + col);
                        float2 zj2 = *(const float2*)(zjr + col);
                        float2 ec2 = *(const float2*)(crow + col);
                        float2 er2 = *(const float2*)(erow + col);
                        float2 o;
                        o.x = acc[mt][nt][h * 2]     + zi2.x + zj2.x + ec2.x + er2.x;
                        o.y = acc[mt][nt][h * 2 + 1] + zi2.y + zj2.y + ec2.y + er2.y;
                        *(float2*)(orow + col) = o;
                    }
                }
                // mirror: z[j0+jg, i0+row_l, :]  (zx symmetric)
                if (mirror) {
                    int cp = cj[jg] * 2 + ci;
                    int rp = samec ? (32 - dcl) : 65;
                    const float* erow = E_rp + (size_t)rp * C_Z;
                    const float* crow = ecp_s + cp * 132;
                    const float* zjr  = g_zjb + (size_t)(i0 + row_l) * C_Z;
                    const float* zir  = zib_s + jg * C_Z;
                    float* orow = out_z + ((size_t)(j0 + jg) * L_RES + (i0 + row_l)) * C_Z;
                    #pragma unroll
                    for (int nt = 0; nt < 4; nt++) {
                        int col = wn * 32 + nt * 8 + tig * 2;
                        float2 zi2 = *(const float2*)(zir + col);
                        float2 zj2 = *(const float2*)(zjr + col);
                        float2 ec2 = *(const float2*)(crow + col);
                        float2 er2 = *(const float2*)(erow + col);
                        float2 o;
                        o.x = acc[mt][nt][h * 2]     + zi2.x + zj2.x + ec2.x + er2.x;
                        o.y = acc[mt][nt][h * 2 + 1] + zi2.y + zj2.y + ec2.y + er2.y;
                        *(float2*)(orow + col) = o;
                    }
                }
            }
        }
    }
}

// ---------------------------------------------------------------------------
extern "C" void kernel_launch(void* const* d_in, const int* in_sizes, int n_in,
                              void* d_out, int out_size)
{
    const int*   seq     = (const int*)  d_in[0];
    const int*   chain   = (const int*)  d_in[1];
    const int*   ridx    = (const int*)  d_in[2];
    const float* E_aa    = (const float*)d_in[3];
    const float* E_pos   = (const float*)d_in[4];
    const float* E_chain = (const float*)d_in[5];
    const float* E_cp    = (const float*)d_in[6];
    const float* E_rp    = (const float*)d_in[7];
    const float* W_pair  = (const float*)d_in[8];
    const float* b_pair  = (const float*)d_in[9];
    const float* ln_w    = (const float*)d_in[10];
    const float* ln_b    = (const float*)d_in[11];

    float* out_s = (float*)d_out;
    float* out_z = out_s + (size_t)L_RES * C_S;

    static int smem_set = 0;
    if (!smem_set) {
        cudaFuncSetAttribute(pair_kernel, cudaFuncAttributeMaxDynamicSharedMemorySize,
                             SMEM_TOTAL);
        smem_set = 1;
    }

    prep_kernel<<<L_RES, C_S>>>(seq, chain, ridx, E_aa, E_pos, E_chain,
                                W_pair, b_pair, ln_w, ln_b, out_s);
    w3split_kernel<<<C_S, C_Z>>>(W_pair);
    pair_kernel<<<320, 256, SMEM_TOTAL>>>(chain, ridx, E_cp, E_rp, out_z);
}

// round 9
// speedup vs baseline: 1.6921x; 1.6921x over previous
#include <cuda_runtime.h>
#include <cuda_bf16.h>
#include <cuda_fp16.h>
#include <cstdint>

#define L_RES 512
#define C_S   256
#define C_Z   128
#define LN_EPS 1e-5f

#define NUNITS 1280
#define GRID_PAIR 296

// ---------------------------------------------------------------------------
// Device scratch
// ---------------------------------------------------------------------------
__device__ __align__(16) float g_u[L_RES * C_S];        // LayerNorm'd embeddings
__device__ __align__(16) float g_zjb[L_RES * C_Z];      // u @ W2 + b_pair
__device__ __align__(16) float g_zib[L_RES * C_Z];      // u @ W1
__device__ __align__(16) __half g_w3t[C_Z * C_S];       // W3^T fp16  [z][c]

// ---------------------------------------------------------------------------
// Base-PTX tensor helpers (valid on compute_103)
// ---------------------------------------------------------------------------
__device__ __forceinline__ uint32_t smem_u32(const void* p) {
    uint32_t a;
    asm("{ .reg .u64 t; cvta.to.shared.u64 t, %1; cvt.u32.u64 %0, t; }"
        : "=r"(a) : "l"(p));
    return a;
}

__device__ __forceinline__ void ldsm_x4(uint32_t& r0, uint32_t& r1,
                                        uint32_t& r2, uint32_t& r3, uint32_t addr) {
    asm volatile("ldmatrix.sync.aligned.m8n8.x4.shared.b16 {%0,%1,%2,%3}, [%4];"
                 : "=r"(r0), "=r"(r1), "=r"(r2), "=r"(r3) : "r"(addr));
}

__device__ __forceinline__ void mma16816(float* c, const uint32_t* a, const uint32_t* b) {
    asm volatile(
        "mma.sync.aligned.m16n8k16.row.col.f32.f16.f16.f32 "
        "{%0,%1,%2,%3}, {%4,%5,%6,%7}, {%8,%9}, {%0,%1,%2,%3};"
        : "+f"(c[0]), "+f"(c[1]), "+f"(c[2]), "+f"(c[3])
        : "r"(a[0]), "r"(a[1]), "r"(a[2]), "r"(a[3]), "r"(b[0]), "r"(b[1]));
}

// ---------------------------------------------------------------------------
// Kernel 1: gather + LayerNorm + zjb (u@W2 + b) + zib (u@W1)
// ---------------------------------------------------------------------------
__global__ void prep_kernel(const int* __restrict__ seq,
                            const int* __restrict__ chain,
                            const int* __restrict__ ridx,
                            const float* __restrict__ E_aa,
                            const float* __restrict__ E_pos,
                            const float* __restrict__ E_chain,
                            const float* __restrict__ W_pair,
                            const float* __restrict__ b_pair,
                            const float* __restrict__ ln_w,
                            const float* __restrict__ ln_b,
                            float* __restrict__ out_s)
{
    int i = blockIdx.x;
    int t = threadIdx.x;            // 256 threads == C_S

    __shared__ float u_s[C_S];
    __shared__ float red1[8], red2[8];
    __shared__ float mu_sh, rstd_sh;

    int sq = seq[i], ci = chain[i], ri = ridx[i];
    float v = E_aa[sq * C_S + t] + E_pos[ri * C_S + t] + E_chain[ci * C_S + t];
    out_s[i * C_S + t] = v;

    // fused sum + sumsq reduction (single pass)
    float s1 = v, s2 = v * v;
    #pragma unroll
    for (int o = 16; o; o >>= 1) {
        s1 += __shfl_xor_sync(0xffffffffu, s1, o);
        s2 += __shfl_xor_sync(0xffffffffu, s2, o);
    }
    if ((t & 31) == 0) { red1[t >> 5] = s1; red2[t >> 5] = s2; }
    __syncthreads();
    if (t == 0) {
        float a1 = 0.f, a2 = 0.f;
        #pragma unroll
        for (int w = 0; w < 8; w++) { a1 += red1[w]; a2 += red2[w]; }
        float mu = a1 * (1.f / C_S);
        float var = a2 * (1.f / C_S) - mu * mu;
        mu_sh = mu;
        rstd_sh = rsqrtf(var + LN_EPS);
    }
    __syncthreads();

    float uu = (v - mu_sh) * rstd_sh * ln_w[t] + ln_b[t];
    g_u[i * C_S + t] = uu;
    u_s[t] = uu;
    __syncthreads();

    // 8 independent accumulator chains (MLP=8)
    int z = t & (C_Z - 1);
    int base = (t < C_Z) ? C_S : 0;
    const float* Wz = W_pair + (size_t)base * C_Z + z;
    float a[8];
    #pragma unroll
    for (int q = 0; q < 8; q++) a[q] = 0.f;
    #pragma unroll 2
    for (int c = 0; c < C_S; c += 8) {
        #pragma unroll
        for (int q = 0; q < 8; q++)
            a[q] += u_s[c + q] * Wz[(c + q) * C_Z];
    }
    float acc = ((a[0] + a[1]) + (a[2] + a[3])) + ((a[4] + a[5]) + (a[6] + a[7]));
    if (t < C_Z) g_zjb[i * C_Z + z] = acc + b_pair[z];
    else         g_zib[i * C_Z + z] = acc;
}

// ---------------------------------------------------------------------------
// Kernel 2: W3 -> transposed fp16:  g_w3t[z*C_S + c]
// ---------------------------------------------------------------------------
__global__ void w3split_kernel(const float* __restrict__ W_pair)
{
    int c = blockIdx.x;             // 0..255
    int z = threadIdx.x;            // 0..127
    g_w3t[z * C_S + c] = __float2half_rn(W_pair[(2 * C_S + c) * C_Z + z]);
}

// ---------------------------------------------------------------------------
// Kernel 3: persistent symmetric mma.sync fp16 pair kernel.
// 296 CTAs; each stages W3 once and grid-strides over 1280 units.
// Unit = (i-tile of 128, single j): D[128,128] = A' @ W3t,
//   A'[r,c] = fp16(u[i0+r,c]*u[j,c]).
// Units enumerate only j >= i0 (triangular coverage):
//   by=0: j 0..511 | by=1: j 128..511 | by=2: j 256..511 | by=3: j 384..511
// mirror (write z[j,i,:] too) iff j >= i0+128; diagonal tiles direct-only.
// ---------------------------------------------------------------------------
#define NCHUNK 8                      // K chunks of 32

// SMEM layout (bytes)
#define SM_W3H   0                    // [z=128][c=256] fp16 swizzled  65536
#define SM_AP    65536                // 2 bufs x [i=128][128B]        32768
#define SM_ECP   98304                // 4 x 132 f32                    2112
#define SM_ZJB   100416               // 128 f32 zjb[j]                  512
#define SM_ZIBJ  100928               // 128 f32 zib[j]                  512
#define SM_UJ    101440               // 256 f32 u[j]                   1024
#define SM_CH    102464               // 128 int                         512
#define SM_RI    102976               // 128 int                         512
#define SMEM_TOTAL 103488

// swizzled W3 smem byte offset for (z, c16) ; c16 = c/8 in [0,32)
__device__ __forceinline__ uint32_t w3_off(int z, int c16) {
    return (uint32_t)(z * 512 + ((c16 & ~7) + ((c16 ^ (z & 7)) & 7)) * 16);
}
// swizzled A' byte offset for (row, chunk) ; chunk in [0,4)
__device__ __forceinline__ uint32_t ap_off(int row, int ch) {
    return (uint32_t)(row * 128 + (ch ^ (row & 7)) * 16);
}

__device__ __forceinline__ void load_u(float4* ur, int i0, int kcg, int t) {
    const int r = t >> 1, half = t & 1;
    const float4* up = (const float4*)(g_u + (size_t)(i0 + r) * C_S + kcg * 32 + half * 16);
    ur[0] = up[0]; ur[1] = up[1]; ur[2] = up[2]; ur[3] = up[3];
}

__device__ __forceinline__ void pack_store(char* smem, int buf, const float4* ur,
                                           int kcg, int t)
{
    const int r = t >> 1, half = t & 1;
    const int c0 = kcg * 32 + half * 16;
    const float4* jp = (const float4*)((const float*)(smem + SM_UJ) + c0);

    uint32_t hi[8];
    #pragma unroll
    for (int q = 0; q < 4; q++) {
        float4 u = ur[q];
        float4 w = jp[q];
        __half2 h01 = __floats2half2_rn(u.x * w.x, u.y * w.y);
        __half2 h23 = __floats2half2_rn(u.z * w.z, u.w * w.w);
        hi[2 * q]     = *reinterpret_cast<uint32_t*>(&h01);
        hi[2 * q + 1] = *reinterpret_cast<uint32_t*>(&h23);
    }
    char* apc = smem + SM_AP + buf * 16384;
    int ch0 = half * 2;
    *(uint4*)(apc + ap_off(r, ch0))     = make_uint4(hi[0], hi[1], hi[2], hi[3]);
    *(uint4*)(apc + ap_off(r, ch0 + 1)) = make_uint4(hi[4], hi[5], hi[6], hi[7]);
}

__global__ __launch_bounds__(256, 2)
void pair_kernel(const int* __restrict__ chain,
                 const int* __restrict__ ridx,
                 const float* __restrict__ E_cp,
                 const float* __restrict__ E_rp,
                 float* __restrict__ out_z)
{
    extern __shared__ char smem[];
    const uint32_t sbase = smem_u32(smem);
    const int t = threadIdx.x;           // 256
    const int lane = t & 31, wid = t >> 5;
    const int wm = wid >> 2;             // 0..1  (M)
    const int wn = wid & 3;              // 0..3  (N)

    float* ecp_s = (float*)(smem + SM_ECP);
    float* zjb_s = (float*)(smem + SM_ZJB);
    float* zib_s = (float*)(smem + SM_ZIBJ);
    float* uj_s  = (float*)(smem + SM_UJ);
    int*   ch_s  = (int*)  (smem + SM_CH);
    int*   ri_s  = (int*)  (smem + SM_RI);

    // ---- once: stage W3 (swizzled) + E_chainpair ----
    for (int idx = t; idx < 4096; idx += 256) {       // 16B chunks
        int z = idx >> 5, c16 = idx & 31;
        uint4 v = *(const uint4*)(g_w3t + (size_t)z * C_S + c16 * 8);
        *(uint4*)(smem + SM_W3H + w3_off(z, c16)) = v;
    }
    for (int idx = t; idx < 4 * C_Z; idx += 256)
        ecp_s[(idx >> 7) * 132 + (idx & 127)] = E_cp[idx];

    // lane address components (ldmatrix)
    const int arow_l = lane & 15;
    const int achk_l = lane >> 4;
    const int bgrp   = lane >> 3;
    const int bz_l   = ((bgrp >> 1) << 3) + (lane & 7);
    const int bco    = bgrp & 1;

    #pragma unroll 1
    for (int u = blockIdx.x; u < NUNITS; u += GRID_PAIR) {
        // decode unit -> (by, j)
        int by, j;
        if (u < 512)       { by = 0; j = u; }
        else if (u < 896)  { by = 1; j = u - 512 + 128; }
        else if (u < 1152) { by = 2; j = u - 896 + 256; }
        else               { by = 3; j = u - 1152 + 384; }
        const int i0 = by * 128;
        const bool mirror = (j >= i0 + 128);

        __syncthreads();   // previous unit's epilogue done before restaging

        // ---- per-unit staging ----
        if (t < 128) {
            float2 v = *(const float2*)(g_u + (size_t)j * C_S + t * 2);
            *(float2*)(uj_s + t * 2) = v;
            zjb_s[t] = g_zjb[(size_t)j * C_Z + t];
            zib_s[t] = g_zib[(size_t)j * C_Z + t];
        } else {
            int tt = t - 128;
            ch_s[tt] = chain[i0 + tt];
            ri_s[tt] = ridx[i0 + tt];
        }
        const int cjv = chain[j], rjv = ridx[j];

        float4 ur[4];
        load_u(ur, i0, 0, t);
        __syncthreads();

        float acc[4][4][4];
        #pragma unroll
        for (int mt = 0; mt < 4; mt++)
            #pragma unroll
            for (int nt = 0; nt < 4; nt++)
                #pragma unroll
                for (int q = 0; q < 4; q++) acc[mt][nt][q] = 0.f;

        #pragma unroll 1
        for (int kcg = 0; kcg < NCHUNK; kcg++) {
            pack_store(smem, kcg & 1, ur, kcg, t);
            __syncthreads();
            if (kcg < NCHUNK - 1) load_u(ur, i0, kcg + 1, t);

            const uint32_t apb = sbase + SM_AP + (kcg & 1) * 16384;
            #pragma unroll
            for (int kk = 0; kk < 2; kk++) {
                uint32_t bh[4][2];
                #pragma unroll
                for (int pair = 0; pair < 2; pair++) {
                    int z   = wn * 32 + pair * 16 + bz_l;
                    int c16 = kcg * 4 + kk * 2 + bco;
                    uint32_t ad = sbase + SM_W3H + w3_off(z, c16);
                    ldsm_x4(bh[pair*2][0], bh[pair*2][1], bh[pair*2+1][0], bh[pair*2+1][1], ad);
                }
                uint32_t ahf[4][4];
                #pragma unroll
                for (int mt = 0; mt < 4; mt++) {
                    int row = wm * 64 + mt * 16 + arow_l;
                    int chh = kk * 2 + achk_l;
                    ldsm_x4(ahf[mt][0], ahf[mt][1], ahf[mt][2], ahf[mt][3],
                            apb + ap_off(row, chh));
                }
                #pragma unroll
                for (int mt = 0; mt < 4; mt++)
                    #pragma unroll
                    for (int nt = 0; nt < 4; nt++)
                        mma16816(acc[mt][nt], ahf[mt], bh[nt]);
            }
        }

        // ---- epilogue ----
        const int g = lane >> 2, tig = lane & 3;
        #pragma unroll
        for (int mt = 0; mt < 4; mt++) {
            #pragma unroll
            for (int h = 0; h < 2; h++) {
                int row_l = wm * 64 + mt * 16 + g + h * 8;
                int ci = ch_s[row_l], ri = ri_s[row_l];
                int samec = (ci == cjv);
                int dd = ri - rjv;
                int dcl = dd < -32 ? -32 : (dd > 32 ? 32 : dd);

                // direct: z[i0+row_l, j, :]
                {
                    int cp = ci * 2 + cjv;
                    int rp = samec ? (dcl + 32) : 65;
                    const float* erow = E_rp + (size_t)rp * C_Z;
                    const float* crow = ecp_s + cp * 132;
                    const float* zir  = g_zib + (size_t)(i0 + row_l) * C_Z;
                    float* orow = out_z + ((size_t)(i0 + row_l) * L_RES + j) * C_Z;
                    #pragma unroll
                    for (int nt = 0; nt < 4; nt++) {
                        int col = wn * 32 + nt * 8 + tig * 2;
                        float2 zi2 = *(const float2*)(zir + col);
                        float2 zj2 = *(const float2*)(zjb_s + col);
                        float2 ec2 = *(const float2*)(crow + col);
                        float2 er2 = *(const float2*)(erow + col);
                        float2 o;
                        o.x = acc[mt][nt][h * 2]     + zi2.x + zj2.x + ec2.x + er2.x;
                        o.y = acc[mt][nt][h * 2 + 1] + zi2.y + zj2.y + ec2.y + er2.y;
                        *(float2*)(orow + col) = o;
                    }
                }
                // mirror: z[j, i0+row_l, :]
                if (mirror) {
                    int cp = cjv * 2 + ci;
                    int rp = samec ? (32 - dcl) : 65;
                    const float* erow = E_rp + (size_t)rp * C_Z;
                    const float* crow = ecp_s + cp * 132;
                    const float* zjr  = g_zjb + (size_t)(i0 + row_l) * C_Z;
                    float* orow = out_z + ((size_t)j * L_RES + (i0 + row_l)) * C_Z;
                    #pragma unroll
                    for (int nt = 0; nt < 4; nt++) {
                        int col = wn * 32 + nt * 8 + tig * 2;
                        float2 zi2 = *(const float2*)(zib_s + col);
                        float2 zj2 = *(const float2*)(zjr + col);
                        float2 ec2 = *(const float2*)(crow + col);
                        float2 er2 = *(const float2*)(erow + col);
                        float2 o;
                        o.x = acc[mt][nt][h * 2]     + zi2.x + zj2.x + ec2.x + er2.x;
                        o.y = acc[mt][nt][h * 2 + 1] + zi2.y + zj2.y + ec2.y + er2.y;
                        *(float2*)(orow + col) = o;
                    }
                }
            }
        }
    }
}

// ---------------------------------------------------------------------------
extern "C" void kernel_launch(void* const* d_in, const int* in_sizes, int n_in,
                              void* d_out, int out_size)
{
    const int*   seq     = (const int*)  d_in[0];
    const int*   chain   = (const int*)  d_in[1];
    const int*   ridx    = (const int*)  d_in[2];
    const float* E_aa    = (const float*)d_in[3];
    const float* E_pos   = (const float*)d_in[4];
    const float* E_chain = (const float*)d_in[5];
    const float* E_cp    = (const float*)d_in[6];
    const float* E_rp    = (const float*)d_in[7];
    const float* W_pair  = (const float*)d_in[8];
    const float* b_pair  = (const float*)d_in[9];
    const float* ln_w    = (const float*)d_in[10];
    const float* ln_b    = (const float*)d_in[11];

    float* out_s = (float*)d_out;
    float* out_z = out_s + (size_t)L_RES * C_S;

    static int smem_set = 0;
    if (!smem_set) {
        cudaFuncSetAttribute(pair_kernel, cudaFuncAttributeMaxDynamicSharedMemorySize,
                             SMEM_TOTAL);
        smem_set = 1;
    }

    prep_kernel<<<L_RES, C_S>>>(seq, chain, ridx, E_aa, E_pos, E_chain,
                                W_pair, b_pair, ln_w, ln_b, out_s);
    w3split_kernel<<<C_S, C_Z>>>(W_pair);
    pair_kernel<<<GRID_PAIR, 256, SMEM_TOTAL>>>(chain, ridx, E_cp, E_rp, out_z);
}

// round 10
// speedup vs baseline: 2.2005x; 1.3004x over previous
#include <cuda_runtime.h>
#include <cuda_bf16.h>
#include <cuda_fp16.h>
#include <cstdint>

#define L_RES 512
#define C_S   256
#define C_Z   128
#define LN_EPS 1e-5f

#define NUNITS 1280
#define GRID_PAIR 296

// ---------------------------------------------------------------------------
// Device scratch
// ---------------------------------------------------------------------------
__device__ __align__(16) float g_u[L_RES * C_S];         // LayerNorm'd embeddings
__device__ __align__(16) float g_zjb[L_RES * C_Z];       // u @ W2 + b_pair
__device__ __align__(16) float g_zib[L_RES * C_Z];       // u @ W1
__device__ __align__(16) __half g_w3t[C_Z * C_S];        // W3^T fp16 [z][c]
__device__ __align__(16) __half g_u16[L_RES * C_S];      // fp16(u)   [i][c]
__device__ __align__(16) __half g_ball[L_RES * C_Z * C_S]; // B_all[j][z][c] = fp16(u[j,c]*W3[c,z])

// ---------------------------------------------------------------------------
// Base-PTX helpers (valid on compute_103)
// ---------------------------------------------------------------------------
__device__ __forceinline__ uint32_t smem_u32(const void* p) {
    uint32_t a;
    asm("{ .reg .u64 t; cvta.to.shared.u64 t, %1; cvt.u32.u64 %0, t; }"
        : "=r"(a) : "l"(p));
    return a;
}

__device__ __forceinline__ void ldsm_x4(uint32_t& r0, uint32_t& r1,
                                        uint32_t& r2, uint32_t& r3, uint32_t addr) {
    asm volatile("ldmatrix.sync.aligned.m8n8.x4.shared.b16 {%0,%1,%2,%3}, [%4];"
                 : "=r"(r0), "=r"(r1), "=r"(r2), "=r"(r3) : "r"(addr));
}

__device__ __forceinline__ void mma16816(float* c, const uint32_t* a, const uint32_t* b) {
    asm volatile(
        "mma.sync.aligned.m16n8k16.row.col.f32.f16.f16.f32 "
        "{%0,%1,%2,%3}, {%4,%5,%6,%7}, {%8,%9}, {%0,%1,%2,%3};"
        : "+f"(c[0]), "+f"(c[1]), "+f"(c[2]), "+f"(c[3])
        : "r"(a[0]), "r"(a[1]), "r"(a[2]), "r"(a[3]), "r"(b[0]), "r"(b[1]));
}

#define CP_ASYNC16(dst, src) \
    asm volatile("cp.async.cg.shared.global [%0], [%1], 16;" :: "r"(dst), "l"(src))
#define CP_COMMIT() asm volatile("cp.async.commit_group;")
#define CP_WAIT1()  asm volatile("cp.async.wait_group 1;")
#define CP_WAIT0()  asm volatile("cp.async.wait_group 0;")

// ---------------------------------------------------------------------------
// Kernel 1: gather + LayerNorm + u16 + w3t + zjb (u@W2+b) + zib (u@W1)
// ---------------------------------------------------------------------------
__global__ void prep_kernel(const int* __restrict__ seq,
                            const int* __restrict__ chain,
                            const int* __restrict__ ridx,
                            const float* __restrict__ E_aa,
                            const float* __restrict__ E_pos,
                            const float* __restrict__ E_chain,
                            const float* __restrict__ W_pair,
                            const float* __restrict__ b_pair,
                            const float* __restrict__ ln_w,
                            const float* __restrict__ ln_b,
                            float* __restrict__ out_s)
{
    int i = blockIdx.x;
    int t = threadIdx.x;            // 256 threads == C_S

    __shared__ float u_s[C_S];
    __shared__ float red1[8], red2[8];
    __shared__ float mu_sh, rstd_sh;

    // fold former w3split: blocks < 256 own column c=i of W3^T
    if (i < 256 && t < 128)
        g_w3t[t * C_S + i] = __float2half_rn(W_pair[(2 * C_S + i) * C_Z + t]);

    int sq = seq[i], ci = chain[i], ri = ridx[i];
    float v = E_aa[sq * C_S + t] + E_pos[ri * C_S + t] + E_chain[ci * C_S + t];
    out_s[i * C_S + t] = v;

    // fused sum + sumsq reduction
    float s1 = v, s2 = v * v;
    #pragma unroll
    for (int o = 16; o; o >>= 1) {
        s1 += __shfl_xor_sync(0xffffffffu, s1, o);
        s2 += __shfl_xor_sync(0xffffffffu, s2, o);
    }
    if ((t & 31) == 0) { red1[t >> 5] = s1; red2[t >> 5] = s2; }
    __syncthreads();
    if (t == 0) {
        float a1 = 0.f, a2 = 0.f;
        #pragma unroll
        for (int w = 0; w < 8; w++) { a1 += red1[w]; a2 += red2[w]; }
        float mu = a1 * (1.f / C_S);
        float var = a2 * (1.f / C_S) - mu * mu;
        mu_sh = mu;
        rstd_sh = rsqrtf(var + LN_EPS);
    }
    __syncthreads();

    float uu = (v - mu_sh) * rstd_sh * ln_w[t] + ln_b[t];
    g_u[i * C_S + t] = uu;
    g_u16[i * C_S + t] = __float2half_rn(uu);
    u_s[t] = uu;
    __syncthreads();

    // 16 independent accumulator chains
    int z = t & (C_Z - 1);
    int base = (t < C_Z) ? C_S : 0;
    const float* Wz = W_pair + (size_t)base * C_Z + z;
    float a[16];
    #pragma unroll
    for (int q = 0; q < 16; q++) a[q] = 0.f;
    #pragma unroll
    for (int c = 0; c < C_S; c += 16) {
        #pragma unroll
        for (int q = 0; q < 16; q++)
            a[q] += u_s[c + q] * Wz[(c + q) * C_Z];
    }
    #pragma unroll
    for (int o = 8; o; o >>= 1)
        #pragma unroll
        for (int q = 0; q < o; q++) a[q] += a[q + o];
    if (t < C_Z) g_zjb[i * C_Z + z] = a[0] + b_pair[z];
    else         g_zib[i * C_Z + z] = a[0];
}

// ---------------------------------------------------------------------------
// Kernel 2: B_all[j][z][c] = fp16( u[j,c] (fp32) * W3t[z,c] )
// grid 512 (one block per j), 256 threads
// ---------------------------------------------------------------------------
__global__ void bprep_kernel()
{
    __shared__ float u_s[C_S];
    const int j = blockIdx.x, t = threadIdx.x;
    if (t < 128) {
        float2 v = *(const float2*)(g_u + (size_t)j * C_S + 2 * t);
        u_s[2 * t] = v.x; u_s[2 * t + 1] = v.y;
    }
    __syncthreads();

    __half* outj = g_ball + (size_t)j * (C_Z * C_S);
    #pragma unroll 4
    for (int k = 0; k < 16; k++) {
        int id = t + k * 256;          // 0..4095 uint4 chunks
        int z = id >> 5, c16 = id & 31;
        uint4 w = *(const uint4*)(g_w3t + (size_t)z * C_S + c16 * 8);
        const __half2* wh = (const __half2*)&w;
        const float2* uf = (const float2*)(u_s + c16 * 8);
        uint4 o;
        __half2* oh = (__half2*)&o;
        #pragma unroll
        for (int e = 0; e < 4; e++) {
            float2 wf = __half22float2(wh[e]);
            float2 u2 = uf[e];
            oh[e] = __floats2half2_rn(wf.x * u2.x, wf.y * u2.y);
        }
        *(uint4*)(outj + (size_t)z * C_S + c16 * 8) = o;
    }
}

// ---------------------------------------------------------------------------
// Kernel 3: persistent symmetric pure-GEMM pair kernel (cp.async streaming).
// Unit = (i-tile of 128, single j): D = u16[i-tile] @ B_all[j]^T.
// Triangular coverage + mirror writes, identical to R9.
// NCHUNK=4 (64-c chunks), A/B tiles 16KB each, double buffered.
// ---------------------------------------------------------------------------
#define NCHUNK 4

// SMEM layout (bytes)
#define SM_A     0                    // 2 bufs x 16384               32768
#define SM_B     32768                // 2 bufs x 16384               32768
#define SM_ECP   65536                // 4 x 132 f32                   2112
#define SM_ZJB   67648                // 128 f32                        512
#define SM_ZIBJ  68160                // 128 f32                        512
#define SM_CH    68672                // 128 int                        512
#define SM_RI    69184                // 128 int                        512
#define SMEM_TOTAL 69696

// swizzled tile byte offset: 128B rows, c16 in [0,8)
__device__ __forceinline__ uint32_t sw_off(int row, int c16) {
    return (uint32_t)(row * 128 + ((c16 ^ (row & 7)) & 7) * 16);
}

__device__ __forceinline__ void stage_async(uint32_t sbase, int buf, int kcg,
                                            int i0, int j, int t)
{
    const int row = t >> 3;            // 0..31
    const int c16 = t & 7;
    const uint32_t dstA = sbase + SM_A + buf * 16384;
    const uint32_t dstB = sbase + SM_B + buf * 16384;
    const __half* srcA = g_u16 + (size_t)(i0 + row) * C_S + kcg * 64 + c16 * 8;
    const __half* srcB = g_ball + (size_t)j * (C_Z * C_S) + (size_t)row * C_S
                         + kcg * 64 + c16 * 8;
    const uint32_t sw = (uint32_t)(((c16 ^ (row & 7)) & 7) * 16 + row * 128);
    #pragma unroll
    for (int q = 0; q < 4; q++) {
        uint32_t off = sw + q * 32 * 128;
        CP_ASYNC16(dstA + off, srcA + (size_t)q * 32 * C_S);
        CP_ASYNC16(dstB + off, srcB + (size_t)q * 32 * C_S);
    }
}

__global__ __launch_bounds__(256, 2)
void pair_kernel(const int* __restrict__ chain,
                 const int* __restrict__ ridx,
                 const float* __restrict__ E_cp,
                 const float* __restrict__ E_rp,
                 float* __restrict__ out_z)
{
    extern __shared__ char smem[];
    const uint32_t sbase = smem_u32(smem);
    const int t = threadIdx.x;           // 256
    const int lane = t & 31, wid = t >> 5;
    const int wm = wid >> 2;             // 0..1  (M)
    const int wn = wid & 3;              // 0..3  (N)

    float* ecp_s = (float*)(smem + SM_ECP);
    float* zjb_s = (float*)(smem + SM_ZJB);
    float* zib_s = (float*)(smem + SM_ZIBJ);
    int*   ch_s  = (int*)  (smem + SM_CH);
    int*   ri_s  = (int*)  (smem + SM_RI);

    for (int idx = t; idx < 4 * C_Z; idx += 256)
        ecp_s[(idx >> 7) * 132 + (idx & 127)] = E_cp[idx];

    // lane address components (ldmatrix)
    const int arow_l = lane & 15;
    const int achk_l = lane >> 4;
    const int bgrp   = lane >> 3;
    const int bz_l   = ((bgrp >> 1) << 3) + (lane & 7);
    const int bco    = bgrp & 1;

    #pragma unroll 1
    for (int u = blockIdx.x; u < NUNITS; u += GRID_PAIR) {
        // decode unit -> (by, j)
        int by, j;
        if (u < 512)       { by = 0; j = u; }
        else if (u < 896)  { by = 1; j = u - 512 + 128; }
        else if (u < 1152) { by = 2; j = u - 896 + 256; }
        else               { by = 3; j = u - 1152 + 384; }
        const int i0 = by * 128;
        const bool mirror = (j >= i0 + 128);

        __syncthreads();   // previous unit fully done before restaging

        stage_async(sbase, 0, 0, i0, j, t); CP_COMMIT();
        stage_async(sbase, 1, 1, i0, j, t); CP_COMMIT();

        if (t < 128) {
            zjb_s[t] = g_zjb[(size_t)j * C_Z + t];
            zib_s[t] = g_zib[(size_t)j * C_Z + t];
        } else {
            int tt = t - 128;
            ch_s[tt] = chain[i0 + tt];
            ri_s[tt] = ridx[i0 + tt];
        }
        const int cjv = chain[j], rjv = ridx[j];

        float acc[4][4][4];
        #pragma unroll
        for (int mt = 0; mt < 4; mt++)
            #pragma unroll
            for (int nt = 0; nt < 4; nt++)
                #pragma unroll
                for (int q = 0; q < 4; q++) acc[mt][nt][q] = 0.f;

        #pragma unroll
        for (int kcg = 0; kcg < NCHUNK; kcg++) {
            if (kcg < NCHUNK - 1) { CP_WAIT1(); } else { CP_WAIT0(); }
            __syncthreads();

            const uint32_t apb = sbase + SM_A + (kcg & 1) * 16384;
            const uint32_t bpb = sbase + SM_B + (kcg & 1) * 16384;
            #pragma unroll
            for (int kk = 0; kk < 4; kk++) {
                uint32_t bh[4][2];
                #pragma unroll
                for (int pair = 0; pair < 2; pair++) {
                    int z = wn * 32 + pair * 16 + bz_l;
                    ldsm_x4(bh[pair*2][0], bh[pair*2][1],
                            bh[pair*2+1][0], bh[pair*2+1][1],
                            bpb + sw_off(z, kk * 2 + bco));
                }
                uint32_t ahf[4][4];
                #pragma unroll
                for (int mt = 0; mt < 4; mt++) {
                    int row = wm * 64 + mt * 16 + arow_l;
                    ldsm_x4(ahf[mt][0], ahf[mt][1], ahf[mt][2], ahf[mt][3],
                            apb + sw_off(row, kk * 2 + achk_l));
                }
                #pragma unroll
                for (int mt = 0; mt < 4; mt++)
                    #pragma unroll
                    for (int nt = 0; nt < 4; nt++)
                        mma16816(acc[mt][nt], ahf[mt], bh[nt]);
            }

            if (kcg < NCHUNK - 2) {
                __syncthreads();           // all warps done reading buf kcg&1
                stage_async(sbase, kcg & 1, kcg + 2, i0, j, t);
                CP_COMMIT();
            }
        }

        // ---- epilogue (identical structure to R9) ----
        const int g = lane >> 2, tig = lane & 3;
        #pragma unroll
        for (int mt = 0; mt < 4; mt++) {
            #pragma unroll
            for (int h = 0; h < 2; h++) {
                int row_l = wm * 64 + mt * 16 + g + h * 8;
                int ci = ch_s[row_l], ri = ri_s[row_l];
                int samec = (ci == cjv);
                int dd = ri - rjv;
                int dcl = dd < -32 ? -32 : (dd > 32 ? 32 : dd);

                // direct: z[i0+row_l, j, :]
                {
                    int cp = ci * 2 + cjv;
                    int rp = samec ? (dcl + 32) : 65;
                    const float* erow = E_rp + (size_t)rp * C_Z;
                    const float* crow = ecp_s + cp * 132;
                    const float* zir  = g_zib + (size_t)(i0 + row_l) * C_Z;
                    float* orow = out_z + ((size_t)(i0 + row_l) * L_RES + j) * C_Z;
                    #pragma unroll
                    for (int nt = 0; nt < 4; nt++) {
                        int col = wn * 32 + nt * 8 + tig * 2;
                        float2 zi2 = *(const float2*)(zir + col);
                        float2 zj2 = *(const float2*)(zjb_s + col);
                        float2 ec2 = *(const float2*)(crow + col);
                        float2 er2 = *(const float2*)(erow + col);
                        float2 o;
                        o.x = acc[mt][nt][h * 2]     + zi2.x + zj2.x + ec2.x + er2.x;
                        o.y = acc[mt][nt][h * 2 + 1] + zi2.y + zj2.y + ec2.y + er2.y;
                        *(float2*)(orow + col) = o;
                    }
                }
                // mirror: z[j, i0+row_l, :]
                if (mirror) {
                    int cp = cjv * 2 + ci;
                    int rp = samec ? (32 - dcl) : 65;
                    const float* erow = E_rp + (size_t)rp * C_Z;
                    const float* crow = ecp_s + cp * 132;
                    const float* zjr  = g_zjb + (size_t)(i0 + row_l) * C_Z;
                    float* orow = out_z + ((size_t)j * L_RES + (i0 + row_l)) * C_Z;
                    #pragma unroll
                    for (int nt = 0; nt < 4; nt++) {
                        int col = wn * 32 + nt * 8 + tig * 2;
                        float2 zi2 = *(const float2*)(zib_s + col);
                        float2 zj2 = *(const float2*)(zjr + col);
                        float2 ec2 = *(const float2*)(crow + col);
                        float2 er2 = *(const float2*)(erow + col);
                        float2 o;
                        o.x = acc[mt][nt][h * 2]     + zi2.x + zj2.x + ec2.x + er2.x;
                        o.y = acc[mt][nt][h * 2 + 1] + zi2.y + zj2.y + ec2.y + er2.y;
                        *(float2*)(orow + col) = o;
                    }
                }
            }
        }
    }
}

// ---------------------------------------------------------------------------
extern "C" void kernel_launch(void* const* d_in, const int* in_sizes, int n_in,
                              void* d_out, int out_size)
{
    const int*   seq     = (const int*)  d_in[0];
    const int*   chain   = (const int*)  d_in[1];
    const int*   ridx    = (const int*)  d_in[2];
    const float* E_aa    = (const float*)d_in[3];
    const float* E_pos   = (const float*)d_in[4];
    const float* E_chain = (const float*)d_in[5];
    const float* E_cp    = (const float*)d_in[6];
    const float* E_rp    = (const float*)d_in[7];
    const float* W_pair  = (const float*)d_in[8];
    const float* b_pair  = (const float*)d_in[9];
    const float* ln_w    = (const float*)d_in[10];
    const float* ln_b    = (const float*)d_in[11];

    float* out_s = (float*)d_out;
    float* out_z = out_s + (size_t)L_RES * C_S;

    static int smem_set = 0;
    if (!smem_set) {
        cudaFuncSetAttribute(pair_kernel, cudaFuncAttributeMaxDynamicSharedMemorySize,
                             SMEM_TOTAL);
        smem_set = 1;
    }

    prep_kernel<<<L_RES, C_S>>>(seq, chain, ridx, E_aa, E_pos, E_chain,
                                W_pair, b_pair, ln_w, ln_b, out_s);
    bprep_kernel<<<L_RES, 256>>>();
    pair_kernel<<<GRID_PAIR, 256, SMEM_TOTAL>>>(chain, ridx, E_cp, E_rp, out_z);
}